// round 2
// baseline (speedup 1.0000x reference)
#include <cuda_runtime.h>
#include <math.h>
#include <stdint.h>

#define B_   4
#define S_   2048
#define E_   1024
#define H_   16
#define DH_  64
#define BH_  (B_*H_)
#define M_   (B_*S_)          // 8192 rows for projection GEMMs

// Scratch (device globals: allocation-free)
__device__ float g_Qh[B_*H_*S_*DH_];   // [B,H,S,DH]
__device__ float g_Kh[B_*H_*S_*DH_];
__device__ float g_Vh[B_*H_*S_*DH_];
__device__ float g_Ctx[B_*S_*E_];      // [B,S,E] context before O-projection

// ---------------------------------------------------------------------------
// Kernel 1: fused QKV projections.  Y = X[M,E] @ W[E,E]^T + b   (NT gemm)
// Output scattered into [B,H,S,DH] head layout.
// grid (M/128, E/128, 3), block 256
// ---------------------------------------------------------------------------
__global__ __launch_bounds__(256) void k_qkv(
    const float* __restrict__ q, const float* __restrict__ k, const float* __restrict__ v,
    const float* __restrict__ wq, const float* __restrict__ bq,
    const float* __restrict__ wk, const float* __restrict__ bk,
    const float* __restrict__ wv, const float* __restrict__ bv)
{
    const float* X; const float* W; const float* bias; float* dst;
    if (blockIdx.z == 0)      { X = q; W = wq; bias = bq; dst = g_Qh; }
    else if (blockIdx.z == 1) { X = k; W = wk; bias = bk; dst = g_Kh; }
    else                      { X = v; W = wv; bias = bv; dst = g_Vh; }

    __shared__ float As[16][128];
    __shared__ float Bs[16][128];
    const int tid = threadIdx.x;
    const int tx = tid & 15, ty = tid >> 4;
    const int row0 = blockIdx.x * 128, col0 = blockIdx.y * 128;

    float acc[8][8];
#pragma unroll
    for (int i = 0; i < 8; i++)
#pragma unroll
        for (int j = 0; j < 8; j++) acc[i][j] = 0.f;

    for (int kt = 0; kt < E_; kt += 16) {
#pragma unroll
        for (int it = 0; it < 2; it++) {
            int f  = tid + it * 256;          // float4 index 0..511
            int r  = f >> 2;
            int c4 = (f & 3) * 4;
            float4 a = *(const float4*)&X[(size_t)(row0 + r) * E_ + kt + c4];
            As[c4+0][r] = a.x; As[c4+1][r] = a.y; As[c4+2][r] = a.z; As[c4+3][r] = a.w;
            float4 b = *(const float4*)&W[(size_t)(col0 + r) * E_ + kt + c4];
            Bs[c4+0][r] = b.x; Bs[c4+1][r] = b.y; Bs[c4+2][r] = b.z; Bs[c4+3][r] = b.w;
        }
        __syncthreads();
#pragma unroll
        for (int kk = 0; kk < 16; kk++) {
            float4 a0 = *(const float4*)&As[kk][ty*8];
            float4 a1 = *(const float4*)&As[kk][ty*8+4];
            float4 b0 = *(const float4*)&Bs[kk][tx*8];
            float4 b1 = *(const float4*)&Bs[kk][tx*8+4];
            float av[8] = {a0.x,a0.y,a0.z,a0.w,a1.x,a1.y,a1.z,a1.w};
            float bv2[8] = {b0.x,b0.y,b0.z,b0.w,b1.x,b1.y,b1.z,b1.w};
#pragma unroll
            for (int i = 0; i < 8; i++)
#pragma unroll
                for (int j = 0; j < 8; j++) acc[i][j] += av[i] * bv2[j];
        }
        __syncthreads();
    }

#pragma unroll
    for (int i = 0; i < 8; i++) {
        int m = row0 + ty*8 + i;
        int b = m >> 11;              // / S_
        int s = m & (S_-1);
#pragma unroll
        for (int j = 0; j < 8; j++) {
            int n = col0 + tx*8 + j;
            int h = n >> 6;
            int d = n & 63;
            dst[(((size_t)b*H_ + h)*S_ + s)*DH_ + d] = acc[i][j] + __ldg(&bias[n]);
        }
    }
}

// ---------------------------------------------------------------------------
// Kernel 2: scores = Q Kh^T / 8 with causal mask, written into attn buffer.
// Per (b,h): M=N=2048, K=64.   grid (16 qtile, 16 ktile, 64 bh), block 256
// Tiles fully above the diagonal are filled with -1e30 (no GEMM).
// ---------------------------------------------------------------------------
__global__ __launch_bounds__(256) void k_scores(float* __restrict__ attn)
{
    const int qt = blockIdx.x, ktile = blockIdx.y, bh = blockIdx.z;
    const int row0 = qt * 128, col0 = ktile * 128;
    float* A = attn + (size_t)bh * S_ * S_;
    const int tid = threadIdx.x;

    if (ktile > qt) {   // fully masked tile
        for (int idx = tid; idx < 128*128; idx += 256) {
            int r = idx >> 7, c = idx & 127;
            A[(size_t)(row0 + r) * S_ + col0 + c] = -1e30f;
        }
        return;
    }

    const float* Q = g_Qh + (size_t)bh * S_ * DH_;
    const float* K = g_Kh + (size_t)bh * S_ * DH_;

    __shared__ float As[16][128];
    __shared__ float Bs[16][128];
    const int tx = tid & 15, ty = tid >> 4;

    float acc[8][8];
#pragma unroll
    for (int i = 0; i < 8; i++)
#pragma unroll
        for (int j = 0; j < 8; j++) acc[i][j] = 0.f;

    for (int kt = 0; kt < DH_; kt += 16) {
#pragma unroll
        for (int it = 0; it < 2; it++) {
            int f  = tid + it * 256;
            int r  = f >> 2;
            int c4 = (f & 3) * 4;
            float4 a = *(const float4*)&Q[(size_t)(row0 + r) * DH_ + kt + c4];
            As[c4+0][r] = a.x; As[c4+1][r] = a.y; As[c4+2][r] = a.z; As[c4+3][r] = a.w;
            float4 b = *(const float4*)&K[(size_t)(col0 + r) * DH_ + kt + c4];
            Bs[c4+0][r] = b.x; Bs[c4+1][r] = b.y; Bs[c4+2][r] = b.z; Bs[c4+3][r] = b.w;
        }
        __syncthreads();
#pragma unroll
        for (int kk = 0; kk < 16; kk++) {
            float4 a0 = *(const float4*)&As[kk][ty*8];
            float4 a1 = *(const float4*)&As[kk][ty*8+4];
            float4 b0 = *(const float4*)&Bs[kk][tx*8];
            float4 b1 = *(const float4*)&Bs[kk][tx*8+4];
            float av[8] = {a0.x,a0.y,a0.z,a0.w,a1.x,a1.y,a1.z,a1.w};
            float bv2[8] = {b0.x,b0.y,b0.z,b0.w,b1.x,b1.y,b1.z,b1.w};
#pragma unroll
            for (int i = 0; i < 8; i++)
#pragma unroll
                for (int j = 0; j < 8; j++) acc[i][j] += av[i] * bv2[j];
        }
        __syncthreads();
    }

#pragma unroll
    for (int i = 0; i < 8; i++) {
        int gi = row0 + ty*8 + i;
#pragma unroll
        for (int j = 0; j < 8; j++) {
            int gj = col0 + tx*8 + j;
            A[(size_t)gi * S_ + gj] = (gj <= gi) ? acc[i][j] * 0.125f : -1e30f;
        }
    }
}

// ---------------------------------------------------------------------------
// Kernel 3: row softmax in place over attn.  One block per row.
// ---------------------------------------------------------------------------
__global__ __launch_bounds__(256) void k_softmax(float* __restrict__ attn)
{
    const size_t row = blockIdx.x;
    float4* p4 = (float4*)(attn + row * (size_t)S_);
    const int t = threadIdx.x;
    __shared__ float red[256];

    float4 a = p4[t];
    float4 b = p4[t + 256];

    float m = fmaxf(fmaxf(fmaxf(a.x, a.y), fmaxf(a.z, a.w)),
                    fmaxf(fmaxf(b.x, b.y), fmaxf(b.z, b.w)));
    red[t] = m; __syncthreads();
    for (int s = 128; s > 0; s >>= 1) {
        if (t < s) red[t] = fmaxf(red[t], red[t + s]);
        __syncthreads();
    }
    m = red[0]; __syncthreads();

    a.x = __expf(a.x - m); a.y = __expf(a.y - m); a.z = __expf(a.z - m); a.w = __expf(a.w - m);
    b.x = __expf(b.x - m); b.y = __expf(b.y - m); b.z = __expf(b.z - m); b.w = __expf(b.w - m);
    float sum = a.x + a.y + a.z + a.w + b.x + b.y + b.z + b.w;
    red[t] = sum; __syncthreads();
    for (int s = 128; s > 0; s >>= 1) {
        if (t < s) red[t] += red[t + s];
        __syncthreads();
    }
    float inv = 1.f / red[0];

    a.x *= inv; a.y *= inv; a.z *= inv; a.w *= inv;
    b.x *= inv; b.y *= inv; b.z *= inv; b.w *= inv;
    p4[t] = a;
    p4[t + 256] = b;
}

// ---------------------------------------------------------------------------
// Kernel 4: context = attn @ V per (b,h).  M=2048, N=64, K=2048 (causal-bounded).
// grid (16 qtile, 1, 64 bh), block 256, 8x4 microtile.
// Writes into g_Ctx with [B,S,E] layout.
// ---------------------------------------------------------------------------
__global__ __launch_bounds__(256) void k_pv(const float* __restrict__ attn)
{
    const int qt = blockIdx.x, bh = blockIdx.z;
    const int row0 = qt * 128;
    const float* P = attn + (size_t)bh * S_ * S_;
    const float* V = g_Vh + (size_t)bh * S_ * DH_;
    const int b = bh >> 4, h = bh & 15;

    __shared__ float Ps[16][128];
    __shared__ float Vs[16][64];
    const int tid = threadIdx.x;
    const int tx = tid & 15, ty = tid >> 4;

    float acc[8][4];
#pragma unroll
    for (int i = 0; i < 8; i++)
#pragma unroll
        for (int j = 0; j < 4; j++) acc[i][j] = 0.f;

    const int kmax = row0 + 128;          // keys beyond query row are exactly 0
    for (int kt = 0; kt < kmax; kt += 16) {
#pragma unroll
        for (int it = 0; it < 2; it++) {
            int f  = tid + it * 256;
            int r  = f >> 2;
            int c4 = (f & 3) * 4;
            float4 a = *(const float4*)&P[(size_t)(row0 + r) * S_ + kt + c4];
            Ps[c4+0][r] = a.x; Ps[c4+1][r] = a.y; Ps[c4+2][r] = a.z; Ps[c4+3][r] = a.w;
        }
        {
            int r  = tid >> 4;             // 0..15
            int c4 = (tid & 15) * 4;       // 0..60
            float4 vv = *(const float4*)&V[(size_t)(kt + r) * DH_ + c4];
            *(float4*)&Vs[r][c4] = vv;
        }
        __syncthreads();
#pragma unroll
        for (int kk = 0; kk < 16; kk++) {
            float4 a0 = *(const float4*)&Ps[kk][ty*8];
            float4 a1 = *(const float4*)&Ps[kk][ty*8+4];
            float4 b0 = *(const float4*)&Vs[kk][tx*4];
            float av[8] = {a0.x,a0.y,a0.z,a0.w,a1.x,a1.y,a1.z,a1.w};
            float bv2[4] = {b0.x,b0.y,b0.z,b0.w};
#pragma unroll
            for (int i = 0; i < 8; i++)
#pragma unroll
                for (int j = 0; j < 4; j++) acc[i][j] += av[i] * bv2[j];
        }
        __syncthreads();
    }

#pragma unroll
    for (int i = 0; i < 8; i++) {
        int srow = row0 + ty*8 + i;
#pragma unroll
        for (int j = 0; j < 4; j++) {
            int d = tx*4 + j;
            g_Ctx[((size_t)(b*S_ + srow))*E_ + h*DH_ + d] = acc[i][j];
        }
    }
}

// ---------------------------------------------------------------------------
// Kernel 5: output projection. out = Ctx[M,E] @ wo[E,E]^T + bo  -> d_out[0..M*E)
// grid (M/128, E/128), block 256
// ---------------------------------------------------------------------------
__global__ __launch_bounds__(256) void k_oproj(
    const float* __restrict__ wo, const float* __restrict__ bo, float* __restrict__ out)
{
    __shared__ float As[16][128];
    __shared__ float Bs[16][128];
    const int tid = threadIdx.x;
    const int tx = tid & 15, ty = tid >> 4;
    const int row0 = blockIdx.x * 128, col0 = blockIdx.y * 128;

    float acc[8][8];
#pragma unroll
    for (int i = 0; i < 8; i++)
#pragma unroll
        for (int j = 0; j < 8; j++) acc[i][j] = 0.f;

    for (int kt = 0; kt < E_; kt += 16) {
#pragma unroll
        for (int it = 0; it < 2; it++) {
            int f  = tid + it * 256;
            int r  = f >> 2;
            int c4 = (f & 3) * 4;
            float4 a = *(const float4*)&g_Ctx[(size_t)(row0 + r) * E_ + kt + c4];
            As[c4+0][r] = a.x; As[c4+1][r] = a.y; As[c4+2][r] = a.z; As[c4+3][r] = a.w;
            float4 b = *(const float4*)&wo[(size_t)(col0 + r) * E_ + kt + c4];
            Bs[c4+0][r] = b.x; Bs[c4+1][r] = b.y; Bs[c4+2][r] = b.z; Bs[c4+3][r] = b.w;
        }
        __syncthreads();
#pragma unroll
        for (int kk = 0; kk < 16; kk++) {
            float4 a0 = *(const float4*)&As[kk][ty*8];
            float4 a1 = *(const float4*)&As[kk][ty*8+4];
            float4 b0 = *(const float4*)&Bs[kk][tx*8];
            float4 b1 = *(const float4*)&Bs[kk][tx*8+4];
            float av[8] = {a0.x,a0.y,a0.z,a0.w,a1.x,a1.y,a1.z,a1.w};
            float bv2[8] = {b0.x,b0.y,b0.z,b0.w,b1.x,b1.y,b1.z,b1.w};
#pragma unroll
            for (int i = 0; i < 8; i++)
#pragma unroll
                for (int j = 0; j < 8; j++) acc[i][j] += av[i] * bv2[j];
        }
        __syncthreads();
    }

#pragma unroll
    for (int i = 0; i < 8; i++) {
        int m = row0 + ty*8 + i;
#pragma unroll
        for (int j = 0; j < 8; j++) {
            int n = col0 + tx*8 + j;
            out[(size_t)m * E_ + n] = acc[i][j] + __ldg(&bo[n]);
        }
    }
}

// ---------------------------------------------------------------------------
extern "C" void kernel_launch(void* const* d_in, const int* in_sizes, int n_in,
                              void* d_out, int out_size)
{
    const float* q  = (const float*)d_in[0];
    const float* k  = (const float*)d_in[1];
    const float* v  = (const float*)d_in[2];
    const float* wq = (const float*)d_in[3];
    const float* bq = (const float*)d_in[4];
    const float* wk = (const float*)d_in[5];
    const float* bk = (const float*)d_in[6];
    const float* wv = (const float*)d_in[7];
    const float* bv = (const float*)d_in[8];
    const float* wo = (const float*)d_in[9];
    const float* bo = (const float*)d_in[10];
    // d_in[11] = causal flag (always 1 for this problem instance)

    float* out  = (float*)d_out;                       // [B,S,E]
    float* attn = out + (size_t)B_ * S_ * E_;          // [B,H,S,S]

    dim3 blk(256);
    k_qkv    <<<dim3(M_/128, E_/128, 3), blk>>>(q, k, v, wq, bq, wk, bk, wv, bv);
    k_scores <<<dim3(S_/128, S_/128, BH_), blk>>>(attn);
    k_softmax<<<dim3(B_*H_*S_), blk>>>(attn);
    k_pv     <<<dim3(S_/128, 1, BH_), blk>>>(attn);
    k_oproj  <<<dim3(M_/128, E_/128), blk>>>(wo, bo, out);
}

// round 3
// speedup vs baseline: 1.9649x; 1.9649x over previous
#include <cuda_runtime.h>
#include <cuda_bf16.h>
#include <math.h>
#include <stdint.h>

#define B_   4
#define S_   2048
#define E_   1024
#define H_   16
#define DH_  64
#define BH_  (B_*H_)
#define M_   (B_*S_)
#define PA   40      // smem pitch (bf16) for 128x32 staging tiles: conflict-free ldmatrix
#define PV   72      // smem pitch (bf16) for 32x64 V tiles (ldmatrix.trans)

// Split-bf16 scratch (device globals: allocation-free)
__device__ __nv_bfloat16 g_Qh[BH_*S_*DH_], g_Ql[BH_*S_*DH_];
__device__ __nv_bfloat16 g_Kh[BH_*S_*DH_], g_Kl[BH_*S_*DH_];
__device__ __nv_bfloat16 g_Vh[BH_*S_*DH_], g_Vl[BH_*S_*DH_];
__device__ __nv_bfloat16 g_Ch[(size_t)M_*E_], g_Cl[(size_t)M_*E_];

static __device__ __forceinline__ uint32_t s2u(const void* p) {
    return (uint32_t)__cvta_generic_to_shared(p);
}
static __device__ __forceinline__ void ldsm4(uint32_t* r, uint32_t a) {
    asm volatile("ldmatrix.sync.aligned.m8n8.x4.shared.b16 {%0,%1,%2,%3}, [%4];\n"
        : "=r"(r[0]), "=r"(r[1]), "=r"(r[2]), "=r"(r[3]) : "r"(a));
}
static __device__ __forceinline__ void ldsm4t(uint32_t* r, uint32_t a) {
    asm volatile("ldmatrix.sync.aligned.m8n8.x4.trans.shared.b16 {%0,%1,%2,%3}, [%4];\n"
        : "=r"(r[0]), "=r"(r[1]), "=r"(r[2]), "=r"(r[3]) : "r"(a));
}
static __device__ __forceinline__ void mma16816(float* c, const uint32_t* a, const uint32_t* b) {
    asm("mma.sync.aligned.m16n8k16.row.col.f32.bf16.bf16.f32 "
        "{%0,%1,%2,%3}, {%4,%5,%6,%7}, {%8,%9}, {%0,%1,%2,%3};\n"
        : "+f"(c[0]), "+f"(c[1]), "+f"(c[2]), "+f"(c[3])
        : "r"(a[0]), "r"(a[1]), "r"(a[2]), "r"(a[3]), "r"(b[0]), "r"(b[1]));
}

// Stage a 128x32 fp32 tile -> split bf16 hi/lo smem tiles ([128][PA]). 512 threads.
static __device__ __forceinline__ void stage_f32(
    const float* __restrict__ src, int ld, int row0, int k0,
    __nv_bfloat16* sh, __nv_bfloat16* sl, int tid)
{
#pragma unroll
    for (int i = 0; i < 2; i++) {
        int idx = tid + i * 512;
        int r = idx >> 3, c4 = (idx & 7) * 4;
        float4 x = *(const float4*)&src[(size_t)(row0 + r) * ld + k0 + c4];
        __nv_bfloat16 h0 = __float2bfloat16(x.x);
        __nv_bfloat16 h1 = __float2bfloat16(x.y);
        __nv_bfloat16 h2 = __float2bfloat16(x.z);
        __nv_bfloat16 h3 = __float2bfloat16(x.w);
        __nv_bfloat16 l0 = __float2bfloat16(x.x - __bfloat162float(h0));
        __nv_bfloat16 l1 = __float2bfloat16(x.y - __bfloat162float(h1));
        __nv_bfloat16 l2 = __float2bfloat16(x.z - __bfloat162float(h2));
        __nv_bfloat16 l3 = __float2bfloat16(x.w - __bfloat162float(h3));
        __nv_bfloat162 t;
        t.x = h0; t.y = h1; *(__nv_bfloat162*)&sh[r * PA + c4] = t;
        t.x = h2; t.y = h3; *(__nv_bfloat162*)&sh[r * PA + c4 + 2] = t;
        t.x = l0; t.y = l1; *(__nv_bfloat162*)&sl[r * PA + c4] = t;
        t.x = l2; t.y = l3; *(__nv_bfloat162*)&sl[r * PA + c4 + 2] = t;
    }
}

// Stage a 128x32 bf16 tile (already split) -> smem [128][PA]. 512 threads.
static __device__ __forceinline__ void stage_b16(
    const __nv_bfloat16* __restrict__ src, int ld, int row0, int k0,
    __nv_bfloat16* s, int tid)
{
    int r = tid >> 2, c8 = (tid & 3) * 8;
    *(uint4*)&s[r * PA + c8] = *(const uint4*)&src[(size_t)(row0 + r) * ld + k0 + c8];
}

// Inner compute for 128x128 block tile, KC=32, warp tile 32x32 (16 warps).
// acc += Ahi*Bhi^T + Alo*Bhi^T + Ahi*Blo^T over the staged KC chunk.
static __device__ __forceinline__ void compute_128x128(
    const __nv_bfloat16* Ah, const __nv_bfloat16* Al,
    const __nv_bfloat16* Bh, const __nv_bfloat16* Bl,
    float (&acc)[2][4][4], int wid, int lane)
{
    const int wm = wid >> 2, wn = wid & 3;
    const int arow = wm * 32 + (lane & 15);
    const int brow = wn * 32 + (lane & 7) + ((lane & 16) ? 8 : 0);
#pragma unroll
    for (int ks = 0; ks < 32; ks += 16) {
        const int ak = ks + ((lane & 16) ? 8 : 0);
        const int bk = ks + ((lane & 8) ? 8 : 0);
        uint32_t ah[2][4], al[2][4], bfh[4][2], bfl[4][2];
#pragma unroll
        for (int mf = 0; mf < 2; mf++) {
            ldsm4(ah[mf], s2u(&Ah[(arow + 16 * mf) * PA + ak]));
            ldsm4(al[mf], s2u(&Al[(arow + 16 * mf) * PA + ak]));
        }
#pragma unroll
        for (int j = 0; j < 2; j++) {
            uint32_t t[4];
            ldsm4(t, s2u(&Bh[(brow + 16 * j) * PA + bk]));
            bfh[2*j][0] = t[0]; bfh[2*j][1] = t[1]; bfh[2*j+1][0] = t[2]; bfh[2*j+1][1] = t[3];
            ldsm4(t, s2u(&Bl[(brow + 16 * j) * PA + bk]));
            bfl[2*j][0] = t[0]; bfl[2*j][1] = t[1]; bfl[2*j+1][0] = t[2]; bfl[2*j+1][1] = t[3];
        }
#pragma unroll
        for (int mf = 0; mf < 2; mf++)
#pragma unroll
            for (int nf = 0; nf < 4; nf++) {
                mma16816(acc[mf][nf], ah[mf], bfh[nf]);
                mma16816(acc[mf][nf], al[mf], bfh[nf]);
                mma16816(acc[mf][nf], ah[mf], bfl[nf]);
            }
    }
}

// ---------------------------------------------------------------------------
// Kernel 1: fused QKV projections. Y = X[M,E] @ W[E,E]^T + b, split-bf16 output
// scattered into [B,H,S,DH] hi/lo arrays. grid(M/128, E/128, 3), 512 thr.
// ---------------------------------------------------------------------------
__global__ __launch_bounds__(512) void k_qkv(
    const float* __restrict__ q, const float* __restrict__ k, const float* __restrict__ v,
    const float* __restrict__ wq, const float* __restrict__ bq,
    const float* __restrict__ wk, const float* __restrict__ bk,
    const float* __restrict__ wv, const float* __restrict__ bv)
{
    const float *X, *W, *bias;
    __nv_bfloat16 *dsth, *dstl;
    if (blockIdx.z == 0)      { X = q; W = wq; bias = bq; dsth = g_Qh; dstl = g_Ql; }
    else if (blockIdx.z == 1) { X = k; W = wk; bias = bk; dsth = g_Kh; dstl = g_Kl; }
    else                      { X = v; W = wv; bias = bv; dsth = g_Vh; dstl = g_Vl; }

    __shared__ __nv_bfloat16 Ah[128*PA], Al[128*PA], Bh[128*PA], Bl[128*PA];
    const int tid = threadIdx.x, wid = tid >> 5, lane = tid & 31;
    const int row0 = blockIdx.x * 128, col0 = blockIdx.y * 128;

    float acc[2][4][4];
#pragma unroll
    for (int i = 0; i < 2; i++)
#pragma unroll
        for (int j = 0; j < 4; j++)
#pragma unroll
            for (int e = 0; e < 4; e++) acc[i][j][e] = 0.f;

    for (int kt = 0; kt < E_; kt += 32) {
        stage_f32(X, E_, row0, kt, Ah, Al, tid);
        stage_f32(W, E_, col0, kt, Bh, Bl, tid);
        __syncthreads();
        compute_128x128(Ah, Al, Bh, Bl, acc, wid, lane);
        __syncthreads();
    }

    const int wm = wid >> 2, wn = wid & 3;
    const int g = lane >> 2, c2 = (lane & 3) * 2;
#pragma unroll
    for (int mf = 0; mf < 2; mf++)
#pragma unroll
        for (int nf = 0; nf < 4; nf++)
#pragma unroll
            for (int e = 0; e < 4; e++) {
                int m = row0 + wm * 32 + mf * 16 + g + ((e & 2) ? 8 : 0);
                int n = col0 + wn * 32 + nf * 8 + c2 + (e & 1);
                float val = acc[mf][nf][e] + __ldg(&bias[n]);
                __nv_bfloat16 h = __float2bfloat16(val);
                __nv_bfloat16 l = __float2bfloat16(val - __bfloat162float(h));
                int b = m >> 11, s = m & (S_ - 1);
                int hd = n >> 6, d = n & 63;
                size_t o = (((size_t)(b * H_ + hd)) * S_ + s) * DH_ + d;
                dsth[o] = h; dstl[o] = l;
            }
}

// ---------------------------------------------------------------------------
// Kernel 2: scores = Q K^T / 8 with causal mask -> attn (fp32).
// Masked tiles write 0 (final attn value there). grid(16,16,64), 512 thr.
// ---------------------------------------------------------------------------
__global__ __launch_bounds__(512) void k_scores(float* __restrict__ attn)
{
    const int qt = blockIdx.x, ktile = blockIdx.y, bhd = blockIdx.z;
    const int row0 = qt * 128, col0 = ktile * 128;
    float* A = attn + (size_t)bhd * S_ * S_;
    const int tid = threadIdx.x;

    if (ktile > qt) {   // fully masked: probs are exactly 0 -> write final value
        float4 z = make_float4(0.f, 0.f, 0.f, 0.f);
#pragma unroll
        for (int i = 0; i < 8; i++) {
            int idx = tid + i * 512;
            int r = idx >> 5, c4 = (idx & 31) * 4;
            *(float4*)&A[(size_t)(row0 + r) * S_ + col0 + c4] = z;
        }
        return;
    }

    const __nv_bfloat16* Qh = g_Qh + (size_t)bhd * S_ * DH_;
    const __nv_bfloat16* Ql = g_Ql + (size_t)bhd * S_ * DH_;
    const __nv_bfloat16* Kh = g_Kh + (size_t)bhd * S_ * DH_;
    const __nv_bfloat16* Kl = g_Kl + (size_t)bhd * S_ * DH_;

    __shared__ __nv_bfloat16 Ah[128*PA], Al[128*PA], Bh[128*PA], Bl[128*PA];
    const int wid = tid >> 5, lane = tid & 31;

    float acc[2][4][4];
#pragma unroll
    for (int i = 0; i < 2; i++)
#pragma unroll
        for (int j = 0; j < 4; j++)
#pragma unroll
            for (int e = 0; e < 4; e++) acc[i][j][e] = 0.f;

#pragma unroll
    for (int kt = 0; kt < DH_; kt += 32) {
        stage_b16(Qh, DH_, row0, kt, Ah, tid);
        stage_b16(Ql, DH_, row0, kt, Al, tid);
        stage_b16(Kh, DH_, col0, kt, Bh, tid);
        stage_b16(Kl, DH_, col0, kt, Bl, tid);
        __syncthreads();
        compute_128x128(Ah, Al, Bh, Bl, acc, wid, lane);
        __syncthreads();
    }

    const int wm = wid >> 2, wn = wid & 3;
    const int g = lane >> 2, c2 = (lane & 3) * 2;
#pragma unroll
    for (int mf = 0; mf < 2; mf++)
#pragma unroll
        for (int nf = 0; nf < 4; nf++)
#pragma unroll
            for (int e = 0; e < 4; e++) {
                int gi = row0 + wm * 32 + mf * 16 + g + ((e & 2) ? 8 : 0);
                int gj = col0 + wn * 32 + nf * 8 + c2 + (e & 1);
                A[(size_t)gi * S_ + gj] = (gj <= gi) ? acc[mf][nf][e] * 0.125f : -1e30f;
            }
}

// ---------------------------------------------------------------------------
// Kernel 3: causal-aware row softmax in place. Only first (qt+1)*128 cols of
// each row are touched (beyond is already final 0). One block per row.
// ---------------------------------------------------------------------------
__global__ __launch_bounds__(256) void k_softmax(float* __restrict__ attn)
{
    const int s = blockIdx.x & (S_ - 1);
    const int ncols4 = ((s >> 7) + 1) * 32;          // float4 count, <= 512
    float4* p = (float4*)(attn + (size_t)blockIdx.x * S_);
    const int t = threadIdx.x;
    __shared__ float red[256];

    float4 a0 = make_float4(-1e30f, -1e30f, -1e30f, -1e30f);
    float4 a1 = a0;
    const bool v0 = t < ncols4, v1 = (t + 256) < ncols4;
    if (v0) a0 = p[t];
    if (v1) a1 = p[t + 256];

    float m = fmaxf(fmaxf(fmaxf(a0.x, a0.y), fmaxf(a0.z, a0.w)),
                    fmaxf(fmaxf(a1.x, a1.y), fmaxf(a1.z, a1.w)));
    red[t] = m; __syncthreads();
    for (int st = 128; st > 0; st >>= 1) {
        if (t < st) red[t] = fmaxf(red[t], red[t + st]);
        __syncthreads();
    }
    m = red[0]; __syncthreads();

    a0.x = __expf(a0.x - m); a0.y = __expf(a0.y - m);
    a0.z = __expf(a0.z - m); a0.w = __expf(a0.w - m);
    a1.x = __expf(a1.x - m); a1.y = __expf(a1.y - m);
    a1.z = __expf(a1.z - m); a1.w = __expf(a1.w - m);
    float sum = 0.f;
    if (v0) sum += a0.x + a0.y + a0.z + a0.w;
    if (v1) sum += a1.x + a1.y + a1.z + a1.w;
    red[t] = sum; __syncthreads();
    for (int st = 128; st > 0; st >>= 1) {
        if (t < st) red[t] += red[t + st];
        __syncthreads();
    }
    const float inv = 1.f / red[0];

    a0.x *= inv; a0.y *= inv; a0.z *= inv; a0.w *= inv;
    a1.x *= inv; a1.y *= inv; a1.z *= inv; a1.w *= inv;
    if (v0) p[t] = a0;
    if (v1) p[t + 256] = a1;
}

// ---------------------------------------------------------------------------
// Kernel 4: context = attn @ V per (b,h). Block tile 128(M)x64(N), KC=32,
// causal-bounded K. Output split bf16 into g_Ch/g_Cl [B,S,E]. 512 thr.
// ---------------------------------------------------------------------------
__global__ __launch_bounds__(512) void k_pv(const float* __restrict__ attn)
{
    const int qt = blockIdx.x, bhd = blockIdx.z;
    const int row0 = qt * 128;
    const float* P = attn + (size_t)bhd * S_ * S_;
    const __nv_bfloat16* Vh = g_Vh + (size_t)bhd * S_ * DH_;
    const __nv_bfloat16* Vl = g_Vl + (size_t)bhd * S_ * DH_;
    const int b = bhd >> 4, hd = bhd & 15;

    __shared__ __nv_bfloat16 Ph[128*PA], Pl[128*PA];
    __shared__ __nv_bfloat16 Vsh[32*PV], Vsl[32*PV];
    const int tid = threadIdx.x, wid = tid >> 5, lane = tid & 31;
    const int wm = wid >> 1, wn = wid & 1;

    float acc[4][4];
#pragma unroll
    for (int j = 0; j < 4; j++)
#pragma unroll
        for (int e = 0; e < 4; e++) acc[j][e] = 0.f;

    const int kmax = row0 + 128;
    for (int kt = 0; kt < kmax; kt += 32) {
        stage_f32(P, S_, row0, kt, Ph, Pl, tid);
        {   // stage V chunk [kt..kt+32) x 64, hi (first 256 thr) and lo (last 256)
            int half = tid >> 8;
            int i = tid & 255;
            int r = i >> 3, c8 = (i & 7) * 8;
            const __nv_bfloat16* src = half ? Vl : Vh;
            __nv_bfloat16* dst = half ? Vsl : Vsh;
            *(uint4*)&dst[r * PV + c8] = *(const uint4*)&src[(size_t)(kt + r) * DH_ + c8];
        }
        __syncthreads();

        const int arow = wm * 16 + (lane & 15);
#pragma unroll
        for (int ks = 0; ks < 32; ks += 16) {
            const int ak = ks + ((lane & 16) ? 8 : 0);
            uint32_t ah[4], al[4], bfh[4][2], bfl[4][2];
            ldsm4(ah, s2u(&Ph[arow * PA + ak]));
            ldsm4(al, s2u(&Pl[arow * PA + ak]));
            const int vrow = ks + (lane & 7) + ((lane & 8) ? 8 : 0);
            const int vcol = wn * 32 + ((lane & 16) ? 8 : 0);
#pragma unroll
            for (int j = 0; j < 2; j++) {
                uint32_t t[4];
                ldsm4t(t, s2u(&Vsh[vrow * PV + vcol + 16 * j]));
                bfh[2*j][0] = t[0]; bfh[2*j][1] = t[1]; bfh[2*j+1][0] = t[2]; bfh[2*j+1][1] = t[3];
                ldsm4t(t, s2u(&Vsl[vrow * PV + vcol + 16 * j]));
                bfl[2*j][0] = t[0]; bfl[2*j][1] = t[1]; bfl[2*j+1][0] = t[2]; bfl[2*j+1][1] = t[3];
            }
#pragma unroll
            for (int nf = 0; nf < 4; nf++) {
                mma16816(acc[nf], ah, bfh[nf]);
                mma16816(acc[nf], al, bfh[nf]);
                mma16816(acc[nf], ah, bfl[nf]);
            }
        }
        __syncthreads();
    }

    const int g = lane >> 2, c2 = (lane & 3) * 2;
#pragma unroll
    for (int nf = 0; nf < 4; nf++)
#pragma unroll
        for (int e = 0; e < 4; e++) {
            int row = row0 + wm * 16 + g + ((e & 2) ? 8 : 0);
            int col = wn * 32 + nf * 8 + c2 + (e & 1);
            float val = acc[nf][e];
            __nv_bfloat16 h = __float2bfloat16(val);
            __nv_bfloat16 l = __float2bfloat16(val - __bfloat162float(h));
            size_t o = ((size_t)(b * S_ + row)) * E_ + hd * DH_ + col;
            g_Ch[o] = h; g_Cl[o] = l;
        }
}

// ---------------------------------------------------------------------------
// Kernel 5: out = Ctx[M,E] @ wo[E,E]^T + bo (fp32 out). grid(64,8), 512 thr.
// ---------------------------------------------------------------------------
__global__ __launch_bounds__(512) void k_oproj(
    const float* __restrict__ wo, const float* __restrict__ bo, float* __restrict__ out)
{
    __shared__ __nv_bfloat16 Ah[128*PA], Al[128*PA], Bh[128*PA], Bl[128*PA];
    const int tid = threadIdx.x, wid = tid >> 5, lane = tid & 31;
    const int row0 = blockIdx.x * 128, col0 = blockIdx.y * 128;

    float acc[2][4][4];
#pragma unroll
    for (int i = 0; i < 2; i++)
#pragma unroll
        for (int j = 0; j < 4; j++)
#pragma unroll
            for (int e = 0; e < 4; e++) acc[i][j][e] = 0.f;

    for (int kt = 0; kt < E_; kt += 32) {
        stage_b16(g_Ch, E_, row0, kt, Ah, tid);
        stage_b16(g_Cl, E_, row0, kt, Al, tid);
        stage_f32(wo, E_, col0, kt, Bh, Bl, tid);
        __syncthreads();
        compute_128x128(Ah, Al, Bh, Bl, acc, wid, lane);
        __syncthreads();
    }

    const int wm = wid >> 2, wn = wid & 3;
    const int g = lane >> 2, c2 = (lane & 3) * 2;
#pragma unroll
    for (int mf = 0; mf < 2; mf++)
#pragma unroll
        for (int nf = 0; nf < 4; nf++)
#pragma unroll
            for (int e = 0; e < 4; e++) {
                int m = row0 + wm * 32 + mf * 16 + g + ((e & 2) ? 8 : 0);
                int n = col0 + wn * 32 + nf * 8 + c2 + (e & 1);
                out[(size_t)m * E_ + n] = acc[mf][nf][e] + __ldg(&bo[n]);
            }
}

// ---------------------------------------------------------------------------
extern "C" void kernel_launch(void* const* d_in, const int* in_sizes, int n_in,
                              void* d_out, int out_size)
{
    const float* q  = (const float*)d_in[0];
    const float* k  = (const float*)d_in[1];
    const float* v  = (const float*)d_in[2];
    const float* wq = (const float*)d_in[3];
    const float* bq = (const float*)d_in[4];
    const float* wk = (const float*)d_in[5];
    const float* bk = (const float*)d_in[6];
    const float* wv = (const float*)d_in[7];
    const float* bv = (const float*)d_in[8];
    const float* wo = (const float*)d_in[9];
    const float* bo = (const float*)d_in[10];

    float* out  = (float*)d_out;                       // [B,S,E]
    float* attn = out + (size_t)B_ * S_ * E_;          // [B,H,S,S]

    k_qkv    <<<dim3(M_/128, E_/128, 3), 512>>>(q, k, v, wq, bq, wk, bk, wv, bv);
    k_scores <<<dim3(S_/128, S_/128, BH_), 512>>>(attn);
    k_softmax<<<dim3(BH_*S_), 256>>>(attn);
    k_pv     <<<dim3(S_/128, 1, BH_), 512>>>(attn);
    k_oproj  <<<dim3(M_/128, E_/128), 512>>>(wo, bo, out);
}

// round 7
// speedup vs baseline: 2.4175x; 1.2303x over previous
#include <cuda_runtime.h>
#include <cuda_bf16.h>
#include <math.h>
#include <stdint.h>

#define B_   4
#define S_   2048
#define E_   1024
#define H_   16
#define DH_  64
#define BH_  (B_*H_)
#define M_   (B_*S_)
#define PA   40      // smem pitch (bf16) for KC=32 staging tiles
#define PS   72      // smem pitch (bf16) for KC=64 scores tiles
#define PV   72      // smem pitch (bf16) for 32x64 V tiles (ldmatrix.trans)

#define TS32 (128*PA*2)            // 10240 bytes per 128x32 bf16 tile
#define DSM_GEMM (2*4*TS32)        // 81920: 2 buffers x {Ah,Al,Bh,Bl}
#define TSS  (128*PS*2)            // 18432 bytes per 128x64 bf16 tile
#define DSM_SC (4*TSS)             // 73728
#define TV   (32*PV*2)             // 4608 bytes per 32x64 V tile
#define DSM_PV (2*2*TS32 + 2*2*TV) // 50176: P(2buf x hi/lo) + V(2buf x hi/lo)
#define EPIL_PITCH 132             // fp32 pitch for epilogue staging

// Split-bf16 scratch (device globals: allocation-free)
__device__ __nv_bfloat16 g_Qh[BH_*S_*DH_], g_Ql[BH_*S_*DH_];
__device__ __nv_bfloat16 g_Kh[BH_*S_*DH_], g_Kl[BH_*S_*DH_];
__device__ __nv_bfloat16 g_Vh[BH_*S_*DH_], g_Vl[BH_*S_*DH_];
__device__ __nv_bfloat16 g_Ch[(size_t)M_*E_], g_Cl[(size_t)M_*E_];

static __device__ __forceinline__ uint32_t s2u(const void* p) {
    return (uint32_t)__cvta_generic_to_shared(p);
}
static __device__ __forceinline__ void ldsm4(uint32_t* r, uint32_t a) {
    asm volatile("ldmatrix.sync.aligned.m8n8.x4.shared.b16 {%0,%1,%2,%3}, [%4];\n"
        : "=r"(r[0]), "=r"(r[1]), "=r"(r[2]), "=r"(r[3]) : "r"(a));
}
static __device__ __forceinline__ void ldsm4t(uint32_t* r, uint32_t a) {
    asm volatile("ldmatrix.sync.aligned.m8n8.x4.trans.shared.b16 {%0,%1,%2,%3}, [%4];\n"
        : "=r"(r[0]), "=r"(r[1]), "=r"(r[2]), "=r"(r[3]) : "r"(a));
}
static __device__ __forceinline__ void mma16816(float* c, const uint32_t* a, const uint32_t* b) {
    asm("mma.sync.aligned.m16n8k16.row.col.f32.bf16.bf16.f32 "
        "{%0,%1,%2,%3}, {%4,%5,%6,%7}, {%8,%9}, {%0,%1,%2,%3};\n"
        : "+f"(c[0]), "+f"(c[1]), "+f"(c[2]), "+f"(c[3])
        : "r"(a[0]), "r"(a[1]), "r"(a[2]), "r"(a[3]), "r"(b[0]), "r"(b[1]));
}

static __device__ __forceinline__ void split2(float a, float b, uint32_t& hi, uint32_t& lo) {
    __nv_bfloat16 ha = __float2bfloat16(a), hb = __float2bfloat16(b);
    __nv_bfloat16 la = __float2bfloat16(a - __bfloat162float(ha));
    __nv_bfloat16 lb = __float2bfloat16(b - __bfloat162float(hb));
    __nv_bfloat162 Hh; Hh.x = ha; Hh.y = hb; hi = *(uint32_t*)&Hh;
    __nv_bfloat162 Ll; Ll.x = la; Ll.y = lb; lo = *(uint32_t*)&Ll;
}
static __device__ __forceinline__ void split8(const float4& x0, const float4& x1,
                                              uint4& H, uint4& L) {
    split2(x0.x, x0.y, H.x, L.x);
    split2(x0.z, x0.w, H.y, L.y);
    split2(x1.x, x1.y, H.z, L.z);
    split2(x1.z, x1.w, H.w, L.w);
}

// Warp-tile 32x32 compute over a staged chunk; 16 warps cover 128x128.
template<int PITCH, int KSTEPS>
static __device__ __forceinline__ void compute_tile(
    const __nv_bfloat16* Ah, const __nv_bfloat16* Al,
    const __nv_bfloat16* Bh, const __nv_bfloat16* Bl,
    float (&acc)[2][4][4], int wid, int lane)
{
    const int wm = wid >> 2, wn = wid & 3;
    const int arow = wm * 32 + (lane & 15);
    const int brow = wn * 32 + (lane & 7) + ((lane & 16) ? 8 : 0);
#pragma unroll
    for (int s = 0; s < KSTEPS; s++) {
        const int ks = s * 16;
        const int ak = ks + ((lane & 16) ? 8 : 0);
        const int bk = ks + ((lane & 8) ? 8 : 0);
        uint32_t ah[2][4], al[2][4], bfh[4][2], bfl[4][2];
#pragma unroll
        for (int mf = 0; mf < 2; mf++) {
            ldsm4(ah[mf], s2u(&Ah[(arow + 16 * mf) * PITCH + ak]));
            ldsm4(al[mf], s2u(&Al[(arow + 16 * mf) * PITCH + ak]));
        }
#pragma unroll
        for (int j = 0; j < 2; j++) {
            uint32_t t[4];
            ldsm4(t, s2u(&Bh[(brow + 16 * j) * PITCH + bk]));
            bfh[2*j][0] = t[0]; bfh[2*j][1] = t[1]; bfh[2*j+1][0] = t[2]; bfh[2*j+1][1] = t[3];
            ldsm4(t, s2u(&Bl[(brow + 16 * j) * PITCH + bk]));
            bfl[2*j][0] = t[0]; bfl[2*j][1] = t[1]; bfl[2*j+1][0] = t[2]; bfl[2*j+1][1] = t[3];
        }
#pragma unroll
        for (int mf = 0; mf < 2; mf++)
#pragma unroll
            for (int nf = 0; nf < 4; nf++) {
                mma16816(acc[mf][nf], ah[mf], bfh[nf]);
                mma16816(acc[mf][nf], al[mf], bfh[nf]);
                mma16816(acc[mf][nf], ah[mf], bfl[nf]);
            }
    }
}

// ---------------------------------------------------------------------------
// Kernel 1: fused QKV projections, pipelined. grid(64,8,3), 512 thr, dyn smem.
// ---------------------------------------------------------------------------
__global__ __launch_bounds__(512) void k_qkv(
    const float* __restrict__ q, const float* __restrict__ k, const float* __restrict__ v,
    const float* __restrict__ wq, const float* __restrict__ bq,
    const float* __restrict__ wk, const float* __restrict__ bk,
    const float* __restrict__ wv, const float* __restrict__ bv)
{
    extern __shared__ char dsm[];
    const float *X, *W, *bias;
    __nv_bfloat16 *dsth, *dstl;
    if (blockIdx.z == 0)      { X = q; W = wq; bias = bq; dsth = g_Qh; dstl = g_Ql; }
    else if (blockIdx.z == 1) { X = k; W = wk; bias = bk; dsth = g_Kh; dstl = g_Kl; }
    else                      { X = v; W = wv; bias = bv; dsth = g_Vh; dstl = g_Vl; }

    const int tid = threadIdx.x, wid = tid >> 5, lane = tid & 31;
    const int row0 = blockIdx.x * 128, col0 = blockIdx.y * 128;
    const int r = tid >> 2, c8 = (tid & 3) * 8;

    float4 rA0, rA1, rB0, rB1;
    auto load_regs = [&](int kt) {
        const float* pa = &X[(size_t)(row0 + r) * E_ + kt + c8];
        rA0 = *(const float4*)pa; rA1 = *(const float4*)(pa + 4);
        const float* pb = &W[(size_t)(col0 + r) * E_ + kt + c8];
        rB0 = *(const float4*)pb; rB1 = *(const float4*)(pb + 4);
    };
    auto store_regs = [&](int buf) {
        char* base = dsm + buf * 4 * TS32;
        uint4 H, L;
        split8(rA0, rA1, H, L);
        *(uint4*)(base + (r * PA + c8) * 2) = H;
        *(uint4*)(base + TS32 + (r * PA + c8) * 2) = L;
        split8(rB0, rB1, H, L);
        *(uint4*)(base + 2 * TS32 + (r * PA + c8) * 2) = H;
        *(uint4*)(base + 3 * TS32 + (r * PA + c8) * 2) = L;
    };

    float acc[2][4][4];
#pragma unroll
    for (int i = 0; i < 2; i++)
#pragma unroll
        for (int j = 0; j < 4; j++)
#pragma unroll
            for (int e = 0; e < 4; e++) acc[i][j][e] = 0.f;

    load_regs(0);
    store_regs(0);
    __syncthreads();

    const int NCH = E_ / 32;
    for (int c = 0; c < NCH; c++) {
        if (c + 1 < NCH) load_regs((c + 1) * 32);
        char* base = dsm + (c & 1) * 4 * TS32;
        compute_tile<PA, 2>((__nv_bfloat16*)base,
                            (__nv_bfloat16*)(base + TS32),
                            (__nv_bfloat16*)(base + 2 * TS32),
                            (__nv_bfloat16*)(base + 3 * TS32), acc, wid, lane);
        if (c + 1 < NCH) {
            store_regs((c + 1) & 1);
            __syncthreads();
        }
    }
    __syncthreads();

    // epilogue: acc -> smem fp32 -> coalesced split bf16 head-scatter
    float* st = (float*)dsm;
    {
        const int wm = wid >> 2, wn = wid & 3;
        const int g = lane >> 2, c2 = (lane & 3) * 2;
#pragma unroll
        for (int mf = 0; mf < 2; mf++)
#pragma unroll
            for (int nf = 0; nf < 4; nf++) {
                int row = wm * 32 + mf * 16 + g, col = wn * 32 + nf * 8 + c2;
                *(float2*)&st[row * EPIL_PITCH + col] = make_float2(acc[mf][nf][0], acc[mf][nf][1]);
                *(float2*)&st[(row + 8) * EPIL_PITCH + col] = make_float2(acc[mf][nf][2], acc[mf][nf][3]);
            }
    }
    __syncthreads();
#pragma unroll
    for (int i = 0; i < 4; i++) {
        int idx = tid + i * 512;                 // 2048 groups of 8 cols
        int g8 = idx & 7, hh = (idx >> 3) & 1, m = idx >> 4;
        int cbase = hh * 64 + g8 * 8;
        float4 x0 = *(float4*)&st[m * EPIL_PITCH + cbase];
        float4 x1 = *(float4*)&st[m * EPIL_PITCH + cbase + 4];
        int n0 = col0 + cbase;
        x0.x += __ldg(&bias[n0]);     x0.y += __ldg(&bias[n0 + 1]);
        x0.z += __ldg(&bias[n0 + 2]); x0.w += __ldg(&bias[n0 + 3]);
        x1.x += __ldg(&bias[n0 + 4]); x1.y += __ldg(&bias[n0 + 5]);
        x1.z += __ldg(&bias[n0 + 6]); x1.w += __ldg(&bias[n0 + 7]);
        uint4 Hv, Lv;
        split8(x0, x1, Hv, Lv);
        int mm = row0 + m;
        int b = mm >> 11, s = mm & (S_ - 1);
        int hd = n0 >> 6, d = n0 & 63;
        size_t o = (((size_t)(b * H_ + hd)) * S_ + s) * DH_ + d;
        *(uint4*)&dsth[o] = Hv;
        *(uint4*)&dstl[o] = Lv;
    }
}

// ---------------------------------------------------------------------------
// Kernel 2: scores = Q K^T / 8, causal. Single KC=64 stage. grid(16,16,64).
// ---------------------------------------------------------------------------
__global__ __launch_bounds__(512) void k_scores(float* __restrict__ attn)
{
    extern __shared__ char dsm[];
    const int qt = blockIdx.x, ktile = blockIdx.y, bhd = blockIdx.z;
    const int row0 = qt * 128, col0 = ktile * 128;
    float* A = attn + (size_t)bhd * S_ * S_;
    const int tid = threadIdx.x;

    if (ktile > qt) {   // fully masked: final attn value is exactly 0
        float4 z = make_float4(0.f, 0.f, 0.f, 0.f);
#pragma unroll
        for (int i = 0; i < 8; i++) {
            int idx = tid + i * 512;
            int rr = idx >> 5, c4 = (idx & 31) * 4;
            *(float4*)&A[(size_t)(row0 + rr) * S_ + col0 + c4] = z;
        }
        return;
    }

    const __nv_bfloat16* Qh = g_Qh + (size_t)bhd * S_ * DH_;
    const __nv_bfloat16* Ql = g_Ql + (size_t)bhd * S_ * DH_;
    const __nv_bfloat16* Kh = g_Kh + (size_t)bhd * S_ * DH_;
    const __nv_bfloat16* Kl = g_Kl + (size_t)bhd * S_ * DH_;
    const int wid = tid >> 5, lane = tid & 31;

    // stage all 4 tiles (full K=64) once
    {
        const int r = tid >> 2, c16 = (tid & 3) * 16;
        const __nv_bfloat16* srcs[4] = {Qh, Ql, Kh, Kl};
        const int rows0[4] = {row0, row0, col0, col0};
#pragma unroll
        for (int t = 0; t < 4; t++) {
            __nv_bfloat16* s = (__nv_bfloat16*)(dsm + t * TSS);
            const __nv_bfloat16* src = &srcs[t][(size_t)(rows0[t] + r) * DH_ + c16];
            *(uint4*)&s[r * PS + c16]     = *(const uint4*)src;
            *(uint4*)&s[r * PS + c16 + 8] = *(const uint4*)(src + 8);
        }
    }
    __syncthreads();

    float acc[2][4][4];
#pragma unroll
    for (int i = 0; i < 2; i++)
#pragma unroll
        for (int j = 0; j < 4; j++)
#pragma unroll
            for (int e = 0; e < 4; e++) acc[i][j][e] = 0.f;

    compute_tile<PS, 4>((__nv_bfloat16*)dsm,
                        (__nv_bfloat16*)(dsm + TSS),
                        (__nv_bfloat16*)(dsm + 2 * TSS),
                        (__nv_bfloat16*)(dsm + 3 * TSS), acc, wid, lane);

    const int wm = wid >> 2, wn = wid & 3;
    const int g = lane >> 2, c2 = (lane & 3) * 2;
#pragma unroll
    for (int mf = 0; mf < 2; mf++)
#pragma unroll
        for (int nf = 0; nf < 4; nf++)
#pragma unroll
            for (int e = 0; e < 4; e++) {
                int gi = row0 + wm * 32 + mf * 16 + g + ((e & 2) ? 8 : 0);
                int gj = col0 + wn * 32 + nf * 8 + c2 + (e & 1);
                A[(size_t)gi * S_ + gj] = (gj <= gi) ? acc[mf][nf][e] * 0.125f : -1e30f;
            }
}

// ---------------------------------------------------------------------------
// Kernel 3: causal-aware row softmax in place. One block per row.
// ---------------------------------------------------------------------------
__global__ __launch_bounds__(256) void k_softmax(float* __restrict__ attn)
{
    const int s = blockIdx.x & (S_ - 1);
    const int ncols4 = ((s >> 7) + 1) * 32;
    float4* p = (float4*)(attn + (size_t)blockIdx.x * S_);
    const int t = threadIdx.x;
    __shared__ float red[256];

    float4 a0 = make_float4(-1e30f, -1e30f, -1e30f, -1e30f);
    float4 a1 = a0;
    const bool v0 = t < ncols4, v1 = (t + 256) < ncols4;
    if (v0) a0 = p[t];
    if (v1) a1 = p[t + 256];

    float m = fmaxf(fmaxf(fmaxf(a0.x, a0.y), fmaxf(a0.z, a0.w)),
                    fmaxf(fmaxf(a1.x, a1.y), fmaxf(a1.z, a1.w)));
    red[t] = m; __syncthreads();
    for (int st = 128; st > 0; st >>= 1) {
        if (t < st) red[t] = fmaxf(red[t], red[t + st]);
        __syncthreads();
    }
    m = red[0]; __syncthreads();

    a0.x = __expf(a0.x - m); a0.y = __expf(a0.y - m);
    a0.z = __expf(a0.z - m); a0.w = __expf(a0.w - m);
    a1.x = __expf(a1.x - m); a1.y = __expf(a1.y - m);
    a1.z = __expf(a1.z - m); a1.w = __expf(a1.w - m);
    float sum = 0.f;
    if (v0) sum += a0.x + a0.y + a0.z + a0.w;
    if (v1) sum += a1.x + a1.y + a1.z + a1.w;
    red[t] = sum; __syncthreads();
    for (int st = 128; st > 0; st >>= 1) {
        if (t < st) red[t] += red[t + st];
        __syncthreads();
    }
    const float inv = 1.f / red[0];

    a0.x *= inv; a0.y *= inv; a0.z *= inv; a0.w *= inv;
    a1.x *= inv; a1.y *= inv; a1.z *= inv; a1.w *= inv;
    if (v0) p[t] = a0;
    if (v1) p[t + 256] = a1;
}

// ---------------------------------------------------------------------------
// Kernel 4: context = attn @ V per (b,h), pipelined. grid(16,1,64), 512 thr.
// ---------------------------------------------------------------------------
__global__ __launch_bounds__(512) void k_pv(const float* __restrict__ attn)
{
    extern __shared__ char dsm[];
    const int qt = blockIdx.x, bhd = blockIdx.z;
    const int row0 = qt * 128;
    const float* P = attn + (size_t)bhd * S_ * S_;
    const __nv_bfloat16* Vh = g_Vh + (size_t)bhd * S_ * DH_;
    const __nv_bfloat16* Vl = g_Vl + (size_t)bhd * S_ * DH_;
    const int b = bhd >> 4, hd = bhd & 15;

    const int tid = threadIdx.x, wid = tid >> 5, lane = tid & 31;
    const int wm = wid >> 1, wn = wid & 1;
    const int r = tid >> 2, c8 = (tid & 3) * 8;
    const int vi = tid & 255, vr = vi >> 3, vc8 = (vi & 7) * 8, vhalf = tid >> 8;

    char* Pbuf = dsm;                        // 2 bufs x {Ph, Pl}
    char* Vbuf = dsm + 2 * 2 * TS32;         // 2 bufs x {Vsh, Vsl}

    float4 rP0, rP1;
    uint4 rV;
    auto load_regs = [&](int kt) {
        const float* pp = &P[(size_t)(row0 + r) * S_ + kt + c8];
        rP0 = *(const float4*)pp; rP1 = *(const float4*)(pp + 4);
        rV = *(const uint4*)&(vhalf ? Vl : Vh)[(size_t)(kt + vr) * DH_ + vc8];
    };
    auto store_regs = [&](int buf) {
        char* pb = Pbuf + buf * 2 * TS32;
        uint4 H, L;
        split8(rP0, rP1, H, L);
        *(uint4*)(pb + (r * PA + c8) * 2) = H;
        *(uint4*)(pb + TS32 + (r * PA + c8) * 2) = L;
        char* vb = Vbuf + buf * 2 * TV + vhalf * TV;
        *(uint4*)(vb + (vr * PV + vc8) * 2) = rV;
    };

    float acc[4][4];
#pragma unroll
    for (int j = 0; j < 4; j++)
#pragma unroll
        for (int e = 0; e < 4; e++) acc[j][e] = 0.f;

    load_regs(0);
    store_regs(0);
    __syncthreads();

    const int NCH = (row0 + 128) / 32;       // causal bound
    for (int c = 0; c < NCH; c++) {
        if (c + 1 < NCH) load_regs((c + 1) * 32);
        const __nv_bfloat16* Ph = (__nv_bfloat16*)(Pbuf + (c & 1) * 2 * TS32);
        const __nv_bfloat16* Pl = (__nv_bfloat16*)(Pbuf + (c & 1) * 2 * TS32 + TS32);
        const __nv_bfloat16* Vsh = (__nv_bfloat16*)(Vbuf + (c & 1) * 2 * TV);
        const __nv_bfloat16* Vsl = (__nv_bfloat16*)(Vbuf + (c & 1) * 2 * TV + TV);

        const int arow = wm * 16 + (lane & 15);
#pragma unroll
        for (int ks = 0; ks < 32; ks += 16) {
            const int ak = ks + ((lane & 16) ? 8 : 0);
            uint32_t ah[4], al[4], bfh[4][2], bfl[4][2];
            ldsm4(ah, s2u(&Ph[arow * PA + ak]));
            ldsm4(al, s2u(&Pl[arow * PA + ak]));
            const int vrow = ks + (lane & 7) + ((lane & 8) ? 8 : 0);
            const int vcol = wn * 32 + ((lane & 16) ? 8 : 0);
#pragma unroll
            for (int j = 0; j < 2; j++) {
                uint32_t t[4];
                ldsm4t(t, s2u(&Vsh[vrow * PV + vcol + 16 * j]));
                bfh[2*j][0] = t[0]; bfh[2*j][1] = t[1]; bfh[2*j+1][0] = t[2]; bfh[2*j+1][1] = t[3];
                ldsm4t(t, s2u(&Vsl[vrow * PV + vcol + 16 * j]));
                bfl[2*j][0] = t[0]; bfl[2*j][1] = t[1]; bfl[2*j+1][0] = t[2]; bfl[2*j+1][1] = t[3];
            }
#pragma unroll
            for (int nf = 0; nf < 4; nf++) {
                mma16816(acc[nf], ah, bfh[nf]);
                mma16816(acc[nf], al, bfh[nf]);
                mma16816(acc[nf], ah, bfl[nf]);
            }
        }
        if (c + 1 < NCH) {
            store_regs((c + 1) & 1);
            __syncthreads();
        }
    }

    const int g = lane >> 2, c2 = (lane & 3) * 2;
#pragma unroll
    for (int nf = 0; nf < 4; nf++) {
        int colp = wn * 32 + nf * 8 + c2;
        int rowA = row0 + wm * 16 + g;
        size_t oA = ((size_t)(b * S_ + rowA)) * E_ + hd * DH_ + colp;
        size_t oB = oA + 8 * E_;
        uint32_t h, l;
        split2(acc[nf][0], acc[nf][1], h, l);
        *(uint32_t*)&g_Ch[oA] = h; *(uint32_t*)&g_Cl[oA] = l;
        split2(acc[nf][2], acc[nf][3], h, l);
        *(uint32_t*)&g_Ch[oB] = h; *(uint32_t*)&g_Cl[oB] = l;
    }
}

// ---------------------------------------------------------------------------
// Kernel 5: out = Ctx[M,E] @ wo^T + bo, pipelined. grid(64,8), 512 thr.
// ---------------------------------------------------------------------------
__global__ __launch_bounds__(512) void k_oproj(
    const float* __restrict__ wo, const float* __restrict__ bo, float* __restrict__ out)
{
    extern __shared__ char dsm[];
    const int tid = threadIdx.x, wid = tid >> 5, lane = tid & 31;
    const int row0 = blockIdx.x * 128, col0 = blockIdx.y * 128;
    const int r = tid >> 2, c8 = (tid & 3) * 8;

    uint4 rAh, rAl;
    float4 rB0, rB1;
    auto load_regs = [&](int kt) {
        size_t oa = (size_t)(row0 + r) * E_ + kt + c8;
        rAh = *(const uint4*)&g_Ch[oa];
        rAl = *(const uint4*)&g_Cl[oa];
        const float* pb = &wo[(size_t)(col0 + r) * E_ + kt + c8];
        rB0 = *(const float4*)pb; rB1 = *(const float4*)(pb + 4);
    };
    auto store_regs = [&](int buf) {
        char* base = dsm + buf * 4 * TS32;
        *(uint4*)(base + (r * PA + c8) * 2) = rAh;
        *(uint4*)(base + TS32 + (r * PA + c8) * 2) = rAl;
        uint4 H, L;
        split8(rB0, rB1, H, L);
        *(uint4*)(base + 2 * TS32 + (r * PA + c8) * 2) = H;
        *(uint4*)(base + 3 * TS32 + (r * PA + c8) * 2) = L;
    };

    float acc[2][4][4];
#pragma unroll
    for (int i = 0; i < 2; i++)
#pragma unroll
        for (int j = 0; j < 4; j++)
#pragma unroll
            for (int e = 0; e < 4; e++) acc[i][j][e] = 0.f;

    load_regs(0);
    store_regs(0);
    __syncthreads();

    const int NCH = E_ / 32;
    for (int c = 0; c < NCH; c++) {
        if (c + 1 < NCH) load_regs((c + 1) * 32);
        char* base = dsm + (c & 1) * 4 * TS32;
        compute_tile<PA, 2>((__nv_bfloat16*)base,
                            (__nv_bfloat16*)(base + TS32),
                            (__nv_bfloat16*)(base + 2 * TS32),
                            (__nv_bfloat16*)(base + 3 * TS32), acc, wid, lane);
        if (c + 1 < NCH) {
            store_regs((c + 1) & 1);
            __syncthreads();
        }
    }
    __syncthreads();

    float* st = (float*)dsm;
    {
        const int wm = wid >> 2, wn = wid & 3;
        const int g = lane >> 2, c2 = (lane & 3) * 2;
#pragma unroll
        for (int mf = 0; mf < 2; mf++)
#pragma unroll
            for (int nf = 0; nf < 4; nf++) {
                int row = wm * 32 + mf * 16 + g, col = wn * 32 + nf * 8 + c2;
                *(float2*)&st[row * EPIL_PITCH + col] = make_float2(acc[mf][nf][0], acc[mf][nf][1]);
                *(float2*)&st[(row + 8) * EPIL_PITCH + col] = make_float2(acc[mf][nf][2], acc[mf][nf][3]);
            }
    }
    __syncthreads();
#pragma unroll
    for (int i = 0; i < 8; i++) {
        int idx = tid + i * 512;                 // 4096 float4 groups
        int c4 = idx & 31, m = idx >> 5;
        float4 x = *(float4*)&st[m * EPIL_PITCH + c4 * 4];
        int n0 = col0 + c4 * 4;
        x.x += __ldg(&bo[n0]);     x.y += __ldg(&bo[n0 + 1]);
        x.z += __ldg(&bo[n0 + 2]); x.w += __ldg(&bo[n0 + 3]);
        *(float4*)&out[(size_t)(row0 + m) * E_ + n0] = x;
    }
}

// ---------------------------------------------------------------------------
extern "C" void kernel_launch(void* const* d_in, const int* in_sizes, int n_in,
                              void* d_out, int out_size)
{
    const float* q  = (const float*)d_in[0];
    const float* k  = (const float*)d_in[1];
    const float* v  = (const float*)d_in[2];
    const float* wq = (const float*)d_in[3];
    const float* bq = (const float*)d_in[4];
    const float* wk = (const float*)d_in[5];
    const float* bk = (const float*)d_in[6];
    const float* wv = (const float*)d_in[7];
    const float* bv = (const float*)d_in[8];
    const float* wo = (const float*)d_in[9];
    const float* bo = (const float*)d_in[10];

    float* out  = (float*)d_out;                       // [B,S,E]
    float* attn = out + (size_t)B_ * S_ * E_;          // [B,H,S,S]

    cudaFuncSetAttribute(k_qkv,    cudaFuncAttributeMaxDynamicSharedMemorySize, DSM_GEMM);
    cudaFuncSetAttribute(k_scores, cudaFuncAttributeMaxDynamicSharedMemorySize, DSM_SC);
    cudaFuncSetAttribute(k_pv,     cudaFuncAttributeMaxDynamicSharedMemorySize, DSM_PV);
    cudaFuncSetAttribute(k_oproj,  cudaFuncAttributeMaxDynamicSharedMemorySize, DSM_GEMM);

    k_qkv    <<<dim3(M_/128, E_/128, 3), 512, DSM_GEMM>>>(q, k, v, wq, bq, wk, bk, wv, bv);
    k_scores <<<dim3(S_/128, S_/128, BH_), 512, DSM_SC>>>(attn);
    k_softmax<<<dim3(BH_*S_), 256>>>(attn);
    k_pv     <<<dim3(S_/128, 1, BH_), 512, DSM_PV>>>(attn);
    k_oproj  <<<dim3(M_/128, E_/128), 512, DSM_GEMM>>>(wo, bo, out);
}